// round 9
// baseline (speedup 1.0000x reference)
#include <cuda_runtime.h>
#include <cuda_bf16.h>
#include <math_constants.h>

// N=16384 rows, C=1000 classes, 9 matrices (outputs1..8 + mimic).
// Per row/matrix: margin = (x[target] == top1) ? top1 - top2 : 0
// out_threshold = softmax(margins / 2) per row -> d_out[1 + row*9 + m]
// max_preds = max over all elements of matrices 0..7 -> d_out[0]
//
// Two-phase, warp-decoupled design:
//  Phase 1: task = (matrix, row) per WARP, no shared/no barriers. Margin ->
//           __device__ scratch plane [m][row] (L2-resident). gmax in-register,
//           one atomicMax per warp.
//  Phase 2: 1 thread per row: read 9 margins, softmax, write out. Thread (0,0)
//           finalizes out[0] and resets scratch (stream-ordered, replay-safe).

#define C_DIM   1000
#define CHUNKS  250          // C_DIM / 4 float4 chunks per row
#define N_ROWS  16384
#define NEG_INF (-CUDART_INF_F)
#define ENC_NEG_INF 0x007FFFFFu   // enc_f(-inf)

struct Ptrs { const float* p[9]; };

__device__ unsigned g_max_enc = ENC_NEG_INF;
__device__ float    g_margin[9 * N_ROWS];   // [m][row]

__device__ __forceinline__ unsigned enc_f(float x) {
    unsigned u = __float_as_uint(x);
    return (u & 0x80000000u) ? ~u : (u | 0x80000000u);
}
__device__ __forceinline__ float dec_f(unsigned e) {
    return (e & 0x80000000u) ? __uint_as_float(e ^ 0x80000000u)
                             : __uint_as_float(~e);
}

// accumulate top-2 of a float4 into (t1, t2)
__device__ __forceinline__ void acc4(float4 v, float& t1, float& t2) {
    float hi1 = fmaxf(v.x, v.y), lo1 = fminf(v.x, v.y);
    float hi2 = fmaxf(v.z, v.w), lo2 = fminf(v.z, v.w);
    float m1 = fmaxf(hi1, hi2);
    float m2 = fmaxf(fminf(hi1, hi2), (hi1 >= hi2) ? lo1 : lo2);
    t2 = fmaxf(fminf(t1, m1), fmaxf(t2, m2));
    t1 = fmaxf(t1, m1);
}

__global__ __launch_bounds__(256, 8)
void margin_kernel(Ptrs ptrs, const unsigned* __restrict__ t32, int nrows) {
    const int lane = threadIdx.x & 31;
    const int gw   = blockIdx.x * 8 + (threadIdx.x >> 5);  // global warp id
    const int W    = gridDim.x * 8;
    const int ntasks = nrows * 9;

    // targets dtype detect, once: int64 values < 1000 => all odd words 0
    unsigned odd  = t32[2 * lane + 1];
    unsigned is32 = __reduce_or_sync(0xFFFFFFFFu, odd);

    float gm = NEG_INF;   // lane-0 authoritative running max over matrices 0..7

    for (int task = gw; task < ntasks; task += W) {
        const int m   = task / nrows;           // consecutive warps: same m,
        const int row = task - m * nrows;       // consecutive rows
        const float* rowp = ptrs.p[m] + (size_t)row * C_DIM;
        const float4* rp4 = reinterpret_cast<const float4*>(rowp);

        long long tg;
        if (is32) tg = (long long)((const int*)t32)[row];
        else      tg = ((const long long*)t32)[row];
        float tv = rowp[tg];                    // warp-uniform broadcast load

        // wave A: chunks lane + {0,32,64,96}
        float4 va0 = rp4[lane];
        float4 va1 = rp4[lane + 32];
        float4 va2 = rp4[lane + 64];
        float4 va3 = rp4[lane + 96];
        float t1 = NEG_INF, t2 = NEG_INF;
        acc4(va0, t1, t2);
        acc4(va1, t1, t2);
        acc4(va2, t1, t2);
        acc4(va3, t1, t2);

        // wave B: chunks lane + {128,160,192,224} (last predicated)
        float4 vb0 = rp4[lane + 128];
        float4 vb1 = rp4[lane + 160];
        float4 vb2 = rp4[lane + 192];
        float4 vb3 = (lane + 224 < CHUNKS) ? rp4[lane + 224]
                   : make_float4(NEG_INF, NEG_INF, NEG_INF, NEG_INF);
        acc4(vb0, t1, t2);
        acc4(vb1, t1, t2);
        acc4(vb2, t1, t2);
        acc4(vb3, t1, t2);

        // warp top-2 reduction
#pragma unroll
        for (int off = 16; off > 0; off >>= 1) {
            float o1 = __shfl_down_sync(0xFFFFFFFFu, t1, off);
            float o2 = __shfl_down_sync(0xFFFFFFFFu, t2, off);
            t2 = fmaxf(fminf(t1, o1), fmaxf(t2, o2));
            t1 = fmaxf(t1, o1);
        }
        if (lane == 0) {
            g_margin[m * nrows + row] = (tv == t1) ? (t1 - t2) : 0.0f;
            if (m < 8) gm = fmaxf(gm, t1);      // row max == top1
        }
    }

    if (lane == 0) atomicMax(&g_max_enc, enc_f(gm));
}

__global__ __launch_bounds__(256)
void softmax_kernel(float* __restrict__ out, int nrows) {
    const int row = blockIdx.x * 256 + threadIdx.x;
    if (row < nrows) {
        float m[9];
        float mm = NEG_INF;
#pragma unroll
        for (int i = 0; i < 9; i++) {
            m[i] = g_margin[i * nrows + row];   // coalesced per m-plane, L2-hot
            mm = fmaxf(mm, m[i]);
        }
        float e[9];
        float sum = 0.0f;
#pragma unroll
        for (int i = 0; i < 9; i++) {
            e[i] = __expf((m[i] - mm) * 0.5f);
            sum += e[i];
        }
        float inv = __fdividef(1.0f, sum);
        float* orow = out + 1 + (size_t)row * 9;
#pragma unroll
        for (int i = 0; i < 9; i++) orow[i] = e[i] * inv;
    }
    if (blockIdx.x == 0 && threadIdx.x == 0) {
        // phase 1 complete (stream order): finalize scalar, reset for replay
        out[0] = dec_f(g_max_enc);
        g_max_enc = ENC_NEG_INF;
    }
}

extern "C" void kernel_launch(void* const* d_in, const int* in_sizes, int n_in,
                              void* d_out, int out_size) {
    Ptrs ps;
    for (int i = 0; i < 9; i++) ps.p[i] = (const float*)d_in[i];
    const unsigned* targets = (const unsigned*)d_in[9];
    float* out = (float*)d_out;

    const int N = in_sizes[9];   // 16384 rows

    int sms = 148;
    cudaDeviceGetAttribute(&sms, cudaDevAttrMultiProcessorCount, 0);
    int grid1 = sms * 8;         // 8 blocks/SM, 8 warps/block -> 64 warps/SM

    margin_kernel<<<grid1, 256>>>(ps, targets, N);
    softmax_kernel<<<(N + 255) / 256, 256>>>(out, N);
}

// round 10
// speedup vs baseline: 1.0911x; 1.0911x over previous
#include <cuda_runtime.h>
#include <cuda_bf16.h>
#include <math_constants.h>

// N=16384 rows, C=1000 classes, 9 matrices (outputs1..8 + mimic).
// Per row/matrix: margin = (x[target] == top1) ? top1 - top2 : 0
// out_threshold = softmax(margins / 2) per row -> d_out[1 + row*9 + m]
// max_preds = max over all elements of matrices 0..7 -> d_out[0]
//
// Persistent fused single-kernel (R7 design, re-tuned):
//  - 9 warps/block, warp m owns matrix m; block grid-strides over rows
//  - grid = 1024 (divides N exactly -> 16 rows/block, zero tail imbalance)
//  - __launch_bounds__(288, 7): 63/64 warps per SM resident (regs = 32)
//  - gmax == top1, in-register accumulation, 1 atomic per block
//  - double-buffered s_margin -> one __syncthreads per row
//  - last block finalizes scalar + resets scratch (graph-replay safe)

#define C_DIM  1000
#define CHUNKS 250          // C_DIM / 4 float4 chunks per row
#define BLOCK  288          // 9 warps
#define NEG_INF (-CUDART_INF_F)
#define ENC_NEG_INF 0x007FFFFFu   // enc_f(-inf)

struct Ptrs { const float* p[9]; };

__device__ unsigned g_max_enc = ENC_NEG_INF;
__device__ unsigned g_done    = 0u;

__device__ __forceinline__ unsigned enc_f(float x) {
    unsigned u = __float_as_uint(x);
    return (u & 0x80000000u) ? ~u : (u | 0x80000000u);
}
__device__ __forceinline__ float dec_f(unsigned e) {
    return (e & 0x80000000u) ? __uint_as_float(e ^ 0x80000000u)
                             : __uint_as_float(~e);
}

// accumulate top-2 of a float4 into (t1, t2)
__device__ __forceinline__ void acc4(float4 v, float& t1, float& t2) {
    float hi1 = fmaxf(v.x, v.y), lo1 = fminf(v.x, v.y);
    float hi2 = fmaxf(v.z, v.w), lo2 = fminf(v.z, v.w);
    float m1 = fmaxf(hi1, hi2);
    float m2 = fmaxf(fminf(hi1, hi2), (hi1 >= hi2) ? lo1 : lo2);
    t2 = fmaxf(fminf(t1, m1), fmaxf(t2, m2));
    t1 = fmaxf(t1, m1);
}

__global__ __launch_bounds__(BLOCK, 7)
void margin_softmax_kernel(Ptrs ptrs, const unsigned* __restrict__ t32,
                           float* __restrict__ out, int nrows) {
    const int t    = threadIdx.x;
    const int lane = t & 31;
    const int w    = t >> 5;          // warp index == matrix index 0..8

    __shared__ float s_margin[2][12]; // double-buffered, padded
    __shared__ float s_gm[8];

    // targets dtype detect, once: int64 values < 1000 => all odd words 0
    unsigned odd  = t32[2 * lane + 1];
    unsigned is32 = __reduce_or_sync(0xFFFFFFFFu, odd);

    const float* base = ptrs.p[w];
    float gm = NEG_INF;               // per-warp running max (lane 0 authoritative)

    int it = 0;
    for (int row = blockIdx.x; row < nrows; row += gridDim.x, ++it) {
        long long tg;
        if (is32) tg = (long long)((const int*)t32)[row];
        else      tg = ((const long long*)t32)[row];

        const float* rowp = base + (size_t)row * C_DIM;
        const float4* rp4 = reinterpret_cast<const float4*>(rowp);

        float tv = rowp[tg];          // broadcast load (uniform in warp)

        // wave A: chunks lane + {0,32,64,96}
        float4 va0 = rp4[lane];
        float4 va1 = rp4[lane + 32];
        float4 va2 = rp4[lane + 64];
        float4 va3 = rp4[lane + 96];
        float t1 = NEG_INF, t2 = NEG_INF;
        acc4(va0, t1, t2);
        acc4(va1, t1, t2);
        acc4(va2, t1, t2);
        acc4(va3, t1, t2);

        // wave B: chunks lane + {128,160,192,224} (last predicated)
        float4 vb0 = rp4[lane + 128];
        float4 vb1 = rp4[lane + 160];
        float4 vb2 = rp4[lane + 192];
        float4 vb3 = (lane + 224 < CHUNKS) ? rp4[lane + 224]
                   : make_float4(NEG_INF, NEG_INF, NEG_INF, NEG_INF);
        acc4(vb0, t1, t2);
        acc4(vb1, t1, t2);
        acc4(vb2, t1, t2);
        acc4(vb3, t1, t2);

        // warp top-2 reduction
#pragma unroll
        for (int off = 16; off > 0; off >>= 1) {
            float o1 = __shfl_down_sync(0xFFFFFFFFu, t1, off);
            float o2 = __shfl_down_sync(0xFFFFFFFFu, t2, off);
            t2 = fmaxf(fminf(t1, o1), fmaxf(t2, o2));
            t1 = fmaxf(t1, o1);
        }
        if (lane == 0) {
            s_margin[it & 1][w] = (tv == t1) ? (t1 - t2) : 0.0f;
            gm = fmaxf(gm, t1);       // row max == top1
        }
        __syncthreads();

        if (w == 0) {
            // softmax over 9 margins / T=2, lanes 0..8 (16-lane butterfly)
            float m = (lane < 9) ? s_margin[it & 1][lane] : NEG_INF;
            float mm = m;
#pragma unroll
            for (int off = 8; off > 0; off >>= 1)
                mm = fmaxf(mm, __shfl_xor_sync(0xFFFFFFFFu, mm, off, 16));
            float e = __expf((m - mm) * 0.5f);
            float sum = e;
#pragma unroll
            for (int off = 8; off > 0; off >>= 1)
                sum += __shfl_xor_sync(0xFFFFFFFFu, sum, off, 16);
            if (lane < 9)
                out[1 + (size_t)row * 9 + lane] = __fdividef(e, sum);
        }
        // s_margin WAR across iterations is protected by double buffering:
        // buffer (it&1) is rewritten only after two more barriers.
    }

    // block-level scalar max: one shared write per warp, one atomic per block
    if (lane == 0 && w < 8) s_gm[w] = gm;
    __syncthreads();
    if (t == 0) {
        float g = s_gm[0];
#pragma unroll
        for (int i = 1; i < 8; i++) g = fmaxf(g, s_gm[i]);
        atomicMax(&g_max_enc, enc_f(g));
        __threadfence();
        unsigned done = atomicAdd(&g_done, 1u);
        if (done == gridDim.x - 1) {
            __threadfence();
            unsigned cur = atomicOr(&g_max_enc, 0u);   // atomic read
            out[0] = dec_f(cur);
            // reset scratch for next graph replay
            g_max_enc = ENC_NEG_INF;
            g_done    = 0u;
        }
    }
}

extern "C" void kernel_launch(void* const* d_in, const int* in_sizes, int n_in,
                              void* d_out, int out_size) {
    Ptrs ps;
    for (int i = 0; i < 9; i++) ps.p[i] = (const float*)d_in[i];
    const unsigned* targets = (const unsigned*)d_in[9];
    float* out = (float*)d_out;

    const int N = in_sizes[9];   // 16384 rows

    // 1024 divides N exactly (16 rows/block) and fits one wave at 7 blocks/SM.
    int grid = 1024;
    if (grid > N) grid = N;

    margin_softmax_kernel<<<grid, BLOCK>>>(ps, targets, out, N);
}